// round 3
// baseline (speedup 1.0000x reference)
#include <cuda_runtime.h>

#define B      64
#define TAPE   262144
#define OUT    65536
#define FANIN  16
#define NCOPY  1024   // copy-role blocks inside the fused kernel

// Scratch (allocation-free rule: __device__ globals)
__device__ float g_tape_T[(size_t)TAPE * B];  // 64 MB: tape transposed to [TAPE, B]
__device__ float g_x_T[(size_t)OUT * B];      // 16 MB: results (fallback path only)
__device__ int   g_is64;                      // 1 if index arrays are int64
__device__ int   g_a64[64];                   // per-probe-block votes: arange if int64
__device__ int   g_a32[64];                   // per-probe-block votes: arange if int32

// ---------------------------------------------------------------------------
// N2: transpose tape [B,TAPE] -> g_tape_T [TAPE,B]  (+ embedded probes).
// Blocks 0..63 additionally verify output_indices == arange under both dtype
// interpretations (1024 values each) and block 0 detects the index dtype.
// ---------------------------------------------------------------------------
__global__ void transpose_probe_kernel(const float* __restrict__ tape,
                                       const int* __restrict__ in_idx_w,
                                       const int* __restrict__ out_idx_w) {
    __shared__ float s[64][65];
    __shared__ int sa64, sa32;
    const int t0 = blockIdx.x * 64;
    const int tx = threadIdx.x;        // 0..63
    const int ty = threadIdx.y;        // 0..7
    const int t  = ty * 64 + tx;       // 0..511
    const int bk = blockIdx.x;

    if (bk < 64 && t == 0) { sa64 = 1; sa32 = 1; }

    #pragma unroll
    for (int i = 0; i < 64; i += 8)
        s[tx][ty + i] = tape[(size_t)(ty + i) * TAPE + t0 + tx];
    __syncthreads();

    if (bk < 64) {
        #pragma unroll
        for (int r = 0; r < 2; r++) {
            const int i = bk * 1024 + t + r * 512;
            // int64 arange: low word == i, high word == 0
            if (out_idx_w[2 * i] != i || out_idx_w[2 * i + 1] != 0) sa64 = 0;
            // int32 arange: word == i
            if (out_idx_w[i] != i) sa32 = 0;
        }
        if (bk == 0 && t < 32) {
            // int64 => all high words of (small-valued) indices are zero
            const bool ok = (in_idx_w[2 * t + 1] == 0) &&
                            (in_idx_w[2 * (t + 32) + 1] == 0);
            const unsigned m = __ballot_sync(0xffffffffu, ok);
            if (t == 0) g_is64 = (m == 0xffffffffu) ? 1 : 0;
        }
    }

    #pragma unroll
    for (int i = 0; i < 64; i += 8)
        g_tape_T[(size_t)(t0 + ty + i) * B + tx] = s[ty + i][tx];

    if (bk < 64) {
        __syncthreads();
        if (t == 0) { g_a64[bk] = sa64; g_a32[bk] = sa32; }
    }
}

// ---------------------------------------------------------------------------
// N3: fused gather+dot+act+scatter (4096 blocks) ∥ tape->out copy (1024 blocks).
// Roles interleaved (bid%5==4 -> copy) so DRAM-bound copy overlaps L2-bound
// gather in every wave. When arange: copy covers cols [OUT,TAPE), scatter
// writes cols [0,OUT) directly -> disjoint, race-free, out fully written.
// Fallback: copy covers all cols, gather parks x in g_x_T for N4.
// All streaming traffic uses evict-first hints to keep tape_T L2-resident.
// ---------------------------------------------------------------------------
__global__ void __launch_bounds__(512)
fused_kernel(const float* __restrict__ tape,
             const float* __restrict__ weights,
             const float* __restrict__ bias,
             const void*  __restrict__ input_indices,
             const void*  __restrict__ act_ids,
             float* __restrict__ out) {
    __shared__ int   sa64, sa32;
    __shared__ int   s_idx[256];
    __shared__ float s_w[256];
    __shared__ float s_bias[16];
    __shared__ int   s_act[16];
    __shared__ float sx[16][66];

    const int t = threadIdx.x;
    if (t == 0) { sa64 = 1; sa32 = 1; }
    __syncthreads();
    if (t < 64) { if (!g_a64[t]) sa64 = 0; if (!g_a32[t]) sa32 = 0; }
    __syncthreads();
    const int is64      = g_is64;
    const int is_arange = is64 ? sa64 : sa32;

    const int bid = blockIdx.x;
    if ((bid % 5) == 4) {
        // ---- copy role: stream tape -> out (float4, evict-first) ----
        const int ci = bid / 5;
        const float4* __restrict__ src = (const float4*)tape;
        float4* __restrict__ dst = (float4*)out;
        const int perrow = is_arange ? (TAPE - OUT) / 4 : TAPE / 4;
        const int col0   = is_arange ? OUT / 4 : 0;
        const long long total  = (long long)B * perrow;
        const long long stride = (long long)NCOPY * 512;
        for (long long j = (long long)ci * 512 + t; j < total; j += stride) {
            const int b = (int)(j / perrow);
            const int c = (int)(j % perrow) + col0;
            const size_t off = (size_t)b * (TAPE / 4) + c;
            __stcs(dst + off, __ldcs(src + off));
        }
        return;
    }

    // ---- gather role: 16 warps = 16 outputs ----
    const int gi   = (bid / 5) * 4 + (bid % 5);
    const int o0   = gi * 16;
    const int warp = t >> 5;
    const int lane = t & 31;

    if (t < 256) {
        s_idx[t] = is64 ? (int)((const long long*)input_indices)[(size_t)o0 * FANIN + t]
                        : ((const int*)input_indices)[(size_t)o0 * FANIN + t];
        s_w[t] = weights[(size_t)o0 * FANIN + t];
    } else if (t < 256 + 16) {
        const int j = t - 256;
        s_bias[j] = bias[o0 + j];
        s_act[j]  = is64 ? (int)((const long long*)act_ids)[o0 + j]
                         : ((const int*)act_ids)[o0 + j];
    }
    __syncthreads();

    const float bv = s_bias[warp];
    float2 acc = make_float2(bv, bv);

    #pragma unroll
    for (int f = 0; f < FANIN; f++) {
        const int   idx = s_idx[warp * FANIN + f];
        const float w   = s_w[warp * FANIN + f];
        const float2 v  = ((const float2*)(g_tape_T + (size_t)idx * B))[lane];
        acc.x = fmaf(w, v.x, acc.x);
        acc.y = fmaf(w, v.y, acc.y);
    }

    const int a = s_act[warp];
    if (a == 0) {
        acc.x = fmaxf(acc.x, 0.f);
        acc.y = fmaxf(acc.y, 0.f);
    } else if (a == 1) {
        acc.x = 1.f / (1.f + __expf(-acc.x));
        acc.y = 1.f / (1.f + __expf(-acc.y));
    } else {
        acc.x = tanhf(acc.x);
        acc.y = tanhf(acc.y);
    }

    sx[warp][lane * 2]     = acc.x;
    sx[warp][lane * 2 + 1] = acc.y;
    __syncthreads();

    // Transposed write: thread t -> output o0 + (t&15), batches t>>4 and +32.
    const int j  = t & 15;
    const int b0 = t >> 4;
    if (is_arange) {
        const int oi = o0 + j;   // verified arange: scatter target == own column
        __stcs(out + (size_t)b0 * TAPE + oi,        sx[j][b0]);
        __stcs(out + (size_t)(b0 + 32) * TAPE + oi, sx[j][b0 + 32]);
    } else {
        g_x_T[(size_t)(o0 + j) * B + b0]      = sx[j][b0];
        g_x_T[(size_t)(o0 + j) * B + b0 + 32] = sx[j][b0 + 32];
    }
}

// ---------------------------------------------------------------------------
// N4: fallback scatter (general output_indices). Early-exits when arange.
// ---------------------------------------------------------------------------
__global__ void fallback_scatter_kernel(float* __restrict__ out,
                                        const void* __restrict__ output_indices) {
    __shared__ int sa64, sa32;
    __shared__ float s[32][33];
    const int t = threadIdx.x;   // 256 threads
    if (t == 0) { sa64 = 1; sa32 = 1; }
    __syncthreads();
    if (t < 64) { if (!g_a64[t]) sa64 = 0; if (!g_a32[t]) sa32 = 0; }
    __syncthreads();
    const int is64 = g_is64;
    if (is64 ? sa64 : sa32) return;   // arange handled in fused_kernel

    const int tx = t & 31, ty = t >> 5;   // 32 x 8
    for (int tile = blockIdx.x; tile < (OUT / 32) * (B / 32); tile += gridDim.x) {
        const int o0 = (tile >> 1) * 32;
        const int b0 = (tile & 1) * 32;
        __syncthreads();
        #pragma unroll
        for (int i = 0; i < 32; i += 8)
            s[ty + i][tx] = g_x_T[(size_t)(o0 + ty + i) * B + b0 + tx];
        __syncthreads();
        const int oi = is64 ? (int)((const long long*)output_indices)[o0 + tx]
                            : ((const int*)output_indices)[o0 + tx];
        #pragma unroll
        for (int i = 0; i < 32; i += 8)
            out[(size_t)(b0 + ty + i) * TAPE + oi] = s[tx][ty + i];
    }
}

// ---------------------------------------------------------------------------
extern "C" void kernel_launch(void* const* d_in, const int* in_sizes, int n_in,
                              void* d_out, int out_size) {
    const float* tape           = (const float*)d_in[0];
    const float* weights        = (const float*)d_in[1];
    const float* bias           = (const float*)d_in[2];
    const void*  input_indices  = d_in[3];
    const void*  output_indices = d_in[4];
    const void*  act_ids        = d_in[5];
    float* out = (float*)d_out;

    // N2: transpose + embedded dtype/arange probes
    transpose_probe_kernel<<<TAPE / 64, dim3(64, 8)>>>(
        tape, (const int*)input_indices, (const int*)output_indices);

    // N3: overlapped gather/scatter + copy
    fused_kernel<<<(OUT / 16) + NCOPY, 512>>>(
        tape, weights, bias, input_indices, act_ids, out);

    // N4: general-index fallback scatter (no-op when arange)
    fallback_scatter_kernel<<<256, 256>>>(out, output_indices);
}

// round 4
// speedup vs baseline: 1.0312x; 1.0312x over previous
#include <cuda_runtime.h>

#define B      64
#define TAPE   262144
#define OUT    65536
#define FANIN  16

// Scratch (allocation-free rule: __device__ globals)
__device__ float g_tape_T[(size_t)TAPE * B];  // 64 MB: tape transposed to [TAPE, B]
__device__ float g_x_T[(size_t)OUT * B];      // 16 MB: results (fallback path only)
__device__ int   g_is64;                      // 1 if index arrays are int64
__device__ int   g_a64[64];                   // per-block votes: arange if int64
__device__ int   g_a32[64];                   // per-block votes: arange if int32

// ---------------------------------------------------------------------------
// K1: single pass over tape [B, TAPE]:
//   (a) out = tape        (streaming float4 copy, evict-first)
//   (b) g_tape_T = tape^T (float4 writes, default policy -> stays L2-resident)
//   (c) blocks 0..63 probe output_indices == arange (both dtype readings)
//   (d) block 0 probes index dtype (int64 high words all zero)
// Reads tape exactly once; all gmem ops are 128-bit.
// ---------------------------------------------------------------------------
__global__ void __launch_bounds__(512)
transpose_copy_probe_kernel(const float* __restrict__ tape,
                            float* __restrict__ out,
                            const int* __restrict__ in_idx_w,
                            const int* __restrict__ out_idx_w) {
    __shared__ float s[64][65];      // [col][batch]
    __shared__ int sa64, sa32;
    const int t  = threadIdx.x;      // 0..511
    const int bk = blockIdx.x;
    const int t0 = bk * 64;          // tape-col base of this tile
    if (t == 0) { sa64 = 1; sa32 = 1; }
    __syncthreads();

    // Phase A: float4 load along tape dim; copy to out; stage transposed in smem
    const int q = t & 15;            // col quad (4 cols each)
    const int b = t >> 4;            // 0..31 (batch)
    #pragma unroll
    for (int i = 0; i < 64; i += 32) {
        const size_t off = (size_t)(b + i) * TAPE + t0 + 4 * q;
        const float4 v = __ldcs((const float4*)(tape + off));
        __stcs((float4*)(out + off), v);
        s[4 * q + 0][b + i] = v.x;
        s[4 * q + 1][b + i] = v.y;
        s[4 * q + 2][b + i] = v.z;
        s[4 * q + 3][b + i] = v.w;
    }

    // Embedded probes (overlap the smem staging latency)
    if (bk < 64) {
        #pragma unroll
        for (int r = 0; r < 2; r++) {
            const int i = bk * 1024 + t + r * 512;
            if (out_idx_w[2 * i] != i || out_idx_w[2 * i + 1] != 0) sa64 = 0;
            if (out_idx_w[i] != i) sa32 = 0;
        }
        if (bk == 0 && t < 32) {
            const bool ok = (in_idx_w[2 * t + 1] == 0) &&
                            (in_idx_w[2 * (t + 32) + 1] == 0);
            const unsigned m = __ballot_sync(0xffffffffu, ok);
            if (t == 0) g_is64 = (m == 0xffffffffu) ? 1 : 0;
        }
    }
    __syncthreads();

    // Phase B: write tape_T rows with float4 stores (warp covers 4 rows = 1KB)
    const int c = t >> 3;            // 0..63 (col within tile)
    const int g = t & 7;             // 0..7  (batch octet)
    float4 w0, w1;
    w0.x = s[c][8 * g + 0]; w0.y = s[c][8 * g + 1];
    w0.z = s[c][8 * g + 2]; w0.w = s[c][8 * g + 3];
    w1.x = s[c][8 * g + 4]; w1.y = s[c][8 * g + 5];
    w1.z = s[c][8 * g + 6]; w1.w = s[c][8 * g + 7];
    float4* dst = (float4*)(g_tape_T + (size_t)(t0 + c) * B + 8 * g);
    dst[0] = w0;
    dst[1] = w1;

    if (bk < 64) {
        __syncthreads();
        if (t == 0) { g_a64[bk] = sa64; g_a32[bk] = sa32; }
    }
}

// ---------------------------------------------------------------------------
// K2: fused gather + weighted-sum + activation + scatter.
// Block = 16 warps = 16 outputs; warp w owns output o0+w, lane l accumulates
// batches (2l, 2l+1) as float2 from coalesced 256B rows of L2-resident
// g_tape_T. When output_indices verified arange, results are written straight
// into out (over K1's copy); else parked in g_x_T for K3.
// ---------------------------------------------------------------------------
__global__ void __launch_bounds__(512)
gather_scatter_kernel(const float* __restrict__ weights,
                      const float* __restrict__ bias,
                      const void*  __restrict__ input_indices,
                      const void*  __restrict__ act_ids,
                      float* __restrict__ out) {
    __shared__ int   sa64, sa32;
    __shared__ int   s_idx[256];
    __shared__ float s_w[256];
    __shared__ float s_bias[16];
    __shared__ int   s_act[16];
    __shared__ float sx[16][66];

    const int t = threadIdx.x;
    if (t == 0) { sa64 = 1; sa32 = 1; }
    __syncthreads();
    if (t < 64) { if (!g_a64[t]) sa64 = 0; if (!g_a32[t]) sa32 = 0; }

    const int o0   = blockIdx.x * 16;
    const int is64 = g_is64;

    if (t < 256) {
        s_idx[t] = is64 ? (int)((const long long*)input_indices)[(size_t)o0 * FANIN + t]
                        : ((const int*)input_indices)[(size_t)o0 * FANIN + t];
        s_w[t] = weights[(size_t)o0 * FANIN + t];
    } else if (t < 256 + 16) {
        const int j = t - 256;
        s_bias[j] = bias[o0 + j];
        s_act[j]  = is64 ? (int)((const long long*)act_ids)[o0 + j]
                         : ((const int*)act_ids)[o0 + j];
    }
    __syncthreads();
    const int is_arange = is64 ? sa64 : sa32;

    const int warp = t >> 5;
    const int lane = t & 31;

    const float bv = s_bias[warp];
    float2 acc = make_float2(bv, bv);

    #pragma unroll
    for (int f = 0; f < FANIN; f++) {
        const int   idx = s_idx[warp * FANIN + f];
        const float w   = s_w[warp * FANIN + f];
        const float2 v  = ((const float2*)(g_tape_T + (size_t)idx * B))[lane];
        acc.x = fmaf(w, v.x, acc.x);
        acc.y = fmaf(w, v.y, acc.y);
    }

    const int a = s_act[warp];
    if (a == 0) {
        acc.x = fmaxf(acc.x, 0.f);
        acc.y = fmaxf(acc.y, 0.f);
    } else if (a == 1) {
        acc.x = 1.f / (1.f + __expf(-acc.x));
        acc.y = 1.f / (1.f + __expf(-acc.y));
    } else {
        acc.x = tanhf(acc.x);
        acc.y = tanhf(acc.y);
    }

    sx[warp][lane * 2]     = acc.x;
    sx[warp][lane * 2 + 1] = acc.y;
    __syncthreads();

    // Transposed write: thread t -> output o0 + (t&15), batches t>>4 and +32.
    const int j  = t & 15;
    const int b0 = t >> 4;
    if (is_arange) {
        const int oi = o0 + j;   // verified arange
        __stcs(out + (size_t)b0 * TAPE + oi,        sx[j][b0]);
        __stcs(out + (size_t)(b0 + 32) * TAPE + oi, sx[j][b0 + 32]);
    } else {
        g_x_T[(size_t)(o0 + j) * B + b0]      = sx[j][b0];
        g_x_T[(size_t)(o0 + j) * B + b0 + 32] = sx[j][b0 + 32];
    }
}

// ---------------------------------------------------------------------------
// K3: fallback scatter (general output_indices). Early-exits when arange.
// ---------------------------------------------------------------------------
__global__ void fallback_scatter_kernel(float* __restrict__ out,
                                        const void* __restrict__ output_indices) {
    __shared__ int sa64, sa32;
    __shared__ float s[32][33];
    const int t = threadIdx.x;   // 256 threads
    if (t == 0) { sa64 = 1; sa32 = 1; }
    __syncthreads();
    if (t < 64) { if (!g_a64[t]) sa64 = 0; if (!g_a32[t]) sa32 = 0; }
    __syncthreads();
    const int is64 = g_is64;
    if (is64 ? sa64 : sa32) return;   // arange handled in K2

    const int tx = t & 31, ty = t >> 5;   // 32 x 8
    for (int tile = blockIdx.x; tile < (OUT / 32) * (B / 32); tile += gridDim.x) {
        const int o0 = (tile >> 1) * 32;
        const int b0 = (tile & 1) * 32;
        __syncthreads();
        #pragma unroll
        for (int i = 0; i < 32; i += 8)
            s[ty + i][tx] = g_x_T[(size_t)(o0 + ty + i) * B + b0 + tx];
        __syncthreads();
        const int oi = is64 ? (int)((const long long*)output_indices)[o0 + tx]
                            : ((const int*)output_indices)[o0 + tx];
        #pragma unroll
        for (int i = 0; i < 32; i += 8)
            out[(size_t)(b0 + ty + i) * TAPE + oi] = s[tx][ty + i];
    }
}

// ---------------------------------------------------------------------------
extern "C" void kernel_launch(void* const* d_in, const int* in_sizes, int n_in,
                              void* d_out, int out_size) {
    const float* tape           = (const float*)d_in[0];
    const float* weights        = (const float*)d_in[1];
    const float* bias           = (const float*)d_in[2];
    const void*  input_indices  = d_in[3];
    const void*  output_indices = d_in[4];
    const void*  act_ids        = d_in[5];
    float* out = (float*)d_out;

    // K1: read tape once -> copy to out + transpose to tape_T (+ probes)
    transpose_copy_probe_kernel<<<TAPE / 64, 512>>>(
        tape, out, (const int*)input_indices, (const int*)output_indices);

    // K2: gather + dot + activation + direct scatter (arange fast path)
    gather_scatter_kernel<<<OUT / 16, 512>>>(weights, bias, input_indices,
                                             act_ids, out);

    // K3: general-index fallback scatter (no-op when arange)
    fallback_scatter_kernel<<<256, 256>>>(out, output_indices);
}